// round 14
// baseline (speedup 1.0000x reference)
#include <cuda_runtime.h>
#include <math.h>
#include <stdint.h>

#define B_ 64
#define A_ 8732
#define G_ 50
#define C_ 81

// ---- K1: flattened balanced grid; per-warp contiguous chunks, 3-deep pipes ----
#define TILE8 8
#define NTB 1092                        // ceil(8732/8) tiles per batch (last tile: 4)
#define TOT_T (B_ * NTB)                // 69888 global tiles
#define NBLK 444                        // 3 blocks/SM * 148 -> exactly one wave
#define WPB 8                           // warps per block
#define K1T (WPB * 32)                  // 256
#define NBUF 3
#define ROWF (TILE8 * C_)               // 648 floats (2592 B) per tile buffer
#define BUFB (ROWF * 4)
#define WARPB (NBUF * BUFB)             // 7776 B per warp
#define DYNSMEM (WPB * WARPB)           // 62208 B
#define SCB4 (A_ * C_ / 4)              // 176823 float4 per batch of scores

// ---- K2 config ----
#define K2T 1024
#define NWARP (K2T / 32)
#define N4 (A_ / 4)                     // 2183 float4/uint4 per batch
#define K2_IT ((N4 + K2T - 1) / K2T)    // 3

// Scratch (no device alloc allowed).
//   negative anchor: v = conf >= 0
//   positive anchor: v = -(sl1 + conf) - 2  (<= -2, disjoint)
__device__ float g_work[B_ * A_];
__device__ float g_batch_loss[B_];
__device__ int   g_batch_np[B_];
__device__ int   g_ticket = 0;

__device__ __forceinline__ float fast_ex2(float x)
{
    float r;
    asm("ex2.approx.ftz.f32 %0, %1;" : "=f"(r) : "f"(x));
    return r;
}
__device__ __forceinline__ float fast_rcp(float x)
{
    float r;
    asm("rcp.approx.ftz.f32 %0, %1;" : "=f"(r) : "f"(x));
    return r;
}
__device__ __forceinline__ uint32_t smem_u32(const void* p)
{
    uint32_t a;
    asm("{ .reg .u64 t; cvta.to.shared.u64 t, %1; cvt.u32.u64 %0, t; }" : "=r"(a) : "l"(p));
    return a;
}
__device__ __forceinline__ void cp16(uint32_t dst, const void* src)
{
    asm volatile("cp.async.cg.shared.global [%0], [%1], 16;" :: "r"(dst), "l"(src));
}

// ---------------------------------------------------------------------------
// K1: 444 blocks, each a contiguous chunk of the flattened tile list (crosses
// <=1 batch boundary; both batches' GT data staged up-front). Each WARP owns
// a CONTIGUOUS sub-chunk with a 3-deep cp.async pipeline; the prefetch source
// pointer advances incrementally (162 float4/tile, 81 at batch boundary).
// Four lanes serve one anchor: quarter q splits the 50 GTs (13/13/12/12) and
// 81 classes (21/20/20/20). IoU argmax via inter*rcp(un) on MUFU; partials
// merged via two shfl_xor levels (lower GT index wins ties).
// ---------------------------------------------------------------------------
__global__ void __launch_bounds__(K1T, 3) k1_anchor(
    const float4* __restrict__ pred_boxes,   // [B, A, 4]
    const float*  __restrict__ pred_scores,  // [B, A, C]
    const float4* __restrict__ gt_boxes,     // [B, G, 4]
    const int*    __restrict__ gt_labels)    // [B, G]
{
    extern __shared__ __align__(16) float dyn[];          // WPB * NBUF * ROWF
    __shared__ __align__(16) float4 s_gtb[2][G_];
    __shared__ float s_gta[2][G_];
    __shared__ int   s_gl[2][G_];

    const int tid  = threadIdx.x;
    const int lane = tid & 31;
    const int wid  = tid >> 5;
    const int al   = lane & 7;      // anchor slot in tile
    const int q    = lane >> 3;     // quarter 0..3

    const int t0 = (int)((long)blockIdx.x * TOT_T / NBLK);
    const int t1 = (int)((long)(blockIdx.x + 1) * TOT_T / NBLK);
    const int b_lo = t0 / NTB;
    const int b_hi = (t1 - 1) / NTB;   // b_lo or b_lo+1

    if (tid < G_) {
        #pragma unroll
        for (int j = 0; j < 2; j++) {
            int bb = (j == 0) ? b_lo : b_hi;
            float4 g = gt_boxes[bb * G_ + tid];
            s_gtb[j][tid] = g;
            s_gta[j][tid] = (g.z - g.x) * (g.w - g.y);
            s_gl[j][tid]  = gt_labels[bb * G_ + tid];
        }
    }
    __syncthreads();

    const int gbase = (q < 2) ? q * 13 : 26 + (q - 2) * 12;   // 0,13,26,38
    const int gext  = (q < 2);                                // 13th GT
    const int cbase = (q == 0) ? 0 : 21 + (q - 1) * 20;       // 0,21,41,61

    // per-warp contiguous sub-chunk
    const int span = t1 - t0;
    const int w0 = t0 + (span * wid) / WPB;
    const int w1 = t0 + (span * (wid + 1)) / WPB;

    const uint32_t wbase = smem_u32(dyn) + wid * WARPB;
    const float*   wrow  = dyn + wid * (NBUF * ROWF);
    const float L2E = 1.4426950408889634f;

    // prefetch tracker: pointer advances incrementally
    int bp = w0 / NTB, tpp = w0 - bp * NTB;
    const float4* pp = (const float4*)pred_scores + (size_t)bp * SCB4 + (size_t)tpp * 162;

    auto prefetch = [&](int sel) {
        // global-last tile: only 81 float4 are in-bounds; otherwise read 162
        const int n4 = (bp == B_ - 1 && tpp == NTB - 1) ? 81 : 162;
        const uint32_t dst = wbase + sel * BUFB;
        #pragma unroll
        for (int i = lane; i < ROWF / 4; i += 32)
            if (i < n4) cp16(dst + i * 16, pp + i);
    };
    #define PADV { pp += (tpp == NTB - 1) ? 81 : 162; if (++tpp == NTB) { tpp = 0; bp++; } }

    // prologue: fill 2 pipeline stages
    #pragma unroll
    for (int j = 0; j < NBUF - 1; j++) {
        if (w0 + j < w1) prefetch(j);
        asm volatile("cp.async.commit_group;");
        PADV;
    }

    int bc = w0 / NTB, tc = w0 - bc * NTB;   // compute tracker
    int sel = 0, psel = NBUF - 1;
    for (int t = w0; t < w1; t++) {
        const int nA = (tc == NTB - 1) ? (A_ - (NTB - 1) * TILE8) : TILE8;
        const int ac = min(al, nA - 1);          // clamped, lanes stay convergent
        const int anchor = tc * TILE8 + ac;
        const int bo = bc - b_lo;                // 0 or 1

        const float4 pb = __ldg(pred_boxes + (size_t)bc * A_ + anchor);

        if (t + (NBUF - 1) < w1) prefetch(psel);
        asm volatile("cp.async.commit_group;");
        asm volatile("cp.async.wait_group 2;");
        __syncwarp();

        const float area_a = (pb.z - pb.x) * (pb.w - pb.y);

        // ---- IoU ratio argmax over this quarter's 12-13 GTs (rcp.approx) ----
        float best = -1e30f;
        int bidx = gbase;
        #pragma unroll
        for (int g = 0; g < 12; g++) {
            float4 gb = s_gtb[bo][gbase + g];
            float iw = fmaxf(fminf(pb.z, gb.z) - fmaxf(pb.x, gb.x), 0.0f);
            float ih = fminf(pb.w, gb.w) - fmaxf(pb.y, gb.y);
            float inter = iw * ih;
            float un = (area_a + s_gta[bo][gbase + g]) - inter;   // > 0 always
            float r = inter * fast_rcp(un);
            if (r > best) { best = r; bidx = gbase + g; }
        }
        if (gext) {
            float4 gb = s_gtb[bo][gbase + 12];
            float iw = fmaxf(fminf(pb.z, gb.z) - fmaxf(pb.x, gb.x), 0.0f);
            float ih = fminf(pb.w, gb.w) - fmaxf(pb.y, gb.y);
            float inter = iw * ih;
            float un = (area_a + s_gta[bo][gbase + 12]) - inter;
            float r = inter * fast_rcp(un);
            if (r > best) { best = r; bidx = gbase + 12; }
        }
        // merge quarters (lower index wins ties -> argmax-first semantics)
        #pragma unroll
        for (int off = 8; off <= 16; off <<= 1) {
            float ob = __shfl_xor_sync(0xffffffffu, best, off);
            int   ox = __shfl_xor_sync(0xffffffffu, bidx, off);
            if (ob > best || (ob == best && ox < bidx)) { best = ob; bidx = ox; }
        }
        const bool pos = best > 0.5f;
        const int  tl  = pos ? s_gl[bo][bidx] : 0;

        // ---- softmax quarter: 20(+1) classes from this warp's smem tile ----
        const float* row = wrow + sel * ROWF + ac * C_;
        float s0 = 0.0f, s1 = 0.0f;
        #pragma unroll
        for (int j = 0; j < 20; j += 2) {
            s0 += fast_ex2(row[cbase + j]     * L2E);
            s1 += fast_ex2(row[cbase + j + 1] * L2E);
        }
        float s = s0 + s1;
        if (q == 0) s += fast_ex2(row[20] * L2E);
        s += __shfl_xor_sync(0xffffffffu, s, 8);
        s += __shfl_xor_sync(0xffffffffu, s, 16);
        const float conf = __logf(s) - row[tl];

        // ---- emit (quarter 0, valid lanes only) ----
        if (q == 0 && al < nA) {
            float outv;
            if (tl > 0) {
                float4 gb = s_gtb[bo][bidx];
                float sl1 = 0.0f, d, ad;
                d = pb.x - gb.x; ad = fabsf(d); sl1 += (ad < 1.0f) ? 0.5f * d * d : ad - 0.5f;
                d = pb.y - gb.y; ad = fabsf(d); sl1 += (ad < 1.0f) ? 0.5f * d * d : ad - 0.5f;
                d = pb.z - gb.z; ad = fabsf(d); sl1 += (ad < 1.0f) ? 0.5f * d * d : ad - 0.5f;
                d = pb.w - gb.w; ad = fabsf(d); sl1 += (ad < 1.0f) ? 0.5f * d * d : ad - 0.5f;
                outv = -(sl1 + conf) - 2.0f;
            } else {
                outv = conf;
            }
            g_work[(size_t)bc * A_ + anchor] = outv;
        }
        __syncwarp();   // tile fully consumed before its buffer slot is reused

        sel  = (sel  == NBUF - 1) ? 0 : sel + 1;
        psel = (psel == NBUF - 1) ? 0 : psel + 1;
        if (++tc == NTB) { tc = 0; bc++; }
        PADV;
    }
}

// ---------------------------------------------------------------------------
// K2: per-batch block (1024 threads). Phase A uses WARP-AGGREGATED smem
// atomics (ballot + match_any + leader popc add) because conf values cluster
// into few exponent bins -> plain atomics serialize per-address. Then
// 2x12-bit radix-select with parallel suffix scans, vectorized top-k sum.
// Last block (atomic ticket) combines the 64 batch results into d_out.
// ---------------------------------------------------------------------------
__device__ __forceinline__ unsigned int f2key(float f)
{
    unsigned int b = __float_as_uint(f);
    return (b & 0x80000000u) ? ~b : (b | 0x80000000u);
}
__device__ __forceinline__ float key2f(unsigned int k)
{
    unsigned int b = (k & 0x80000000u) ? (k ^ 0x80000000u) : ~k;
    return __uint_as_float(b);
}

__global__ void __launch_bounds__(K2T) k2_select(float* __restrict__ out)
{
    __shared__ __align__(16) unsigned int keys[A_];       // 34928 B
    __shared__ unsigned int hist[4096];                   // 16384 B
    __shared__ float s_wf[NWARP];
    __shared__ int   s_wi[NWARP];
    __shared__ int   s_woff[NWARP];
    __shared__ unsigned int s_pref;
    __shared__ int   s_kk;
    __shared__ float s_pos;
    __shared__ int   s_np;
    __shared__ int   s_last;
    __shared__ float s_red64f[B_];
    __shared__ int   s_red64i[B_];

    const int b    = blockIdx.x;
    const int tid  = threadIdx.x;
    const int lane = tid & 31;
    const int wrp  = tid >> 5;

    const unsigned int NEG1_KEY = f2key(-1.0f);

    ((uint4*)hist)[tid] = make_uint4(0, 0, 0, 0);
    __syncthreads();

    // ---- Phase A: load + decode + psum/pcnt + warp-aggregated pass-1 hist ----
    const float4* gw4 = (const float4*)(g_work + (size_t)b * A_);
    uint4* keys4 = (uint4*)keys;
    float psum = 0.0f;
    int   pcnt = 0;
    #pragma unroll
    for (int it = 0; it < K2_IT; it++) {
        const int i4 = tid + it * K2T;
        const bool v = i4 < N4;
        uint4 k4 = make_uint4(0, 0, 0, 0);
        if (v) {
            float4 v4 = gw4[i4];
            float vv; bool p;
            vv = v4.x; p = vv <= -1.5f; if (p) { psum += -(vv + 2.0f); pcnt++; }
            k4.x = p ? NEG1_KEY : f2key(vv);
            vv = v4.y; p = vv <= -1.5f; if (p) { psum += -(vv + 2.0f); pcnt++; }
            k4.y = p ? NEG1_KEY : f2key(vv);
            vv = v4.z; p = vv <= -1.5f; if (p) { psum += -(vv + 2.0f); pcnt++; }
            k4.z = p ? NEG1_KEY : f2key(vv);
            vv = v4.w; p = vv <= -1.5f; if (p) { psum += -(vv + 2.0f); pcnt++; }
            k4.w = p ? NEG1_KEY : f2key(vv);
            keys4[i4] = k4;
        }
        const unsigned int act = __ballot_sync(0xffffffffu, v);
        if (v) {
            unsigned int bin, m;
            bin = k4.x >> 20; m = __match_any_sync(act, bin);
            if ((int)(__ffs(m) - 1) == lane) atomicAdd(&hist[bin], (unsigned)__popc(m));
            bin = k4.y >> 20; m = __match_any_sync(act, bin);
            if ((int)(__ffs(m) - 1) == lane) atomicAdd(&hist[bin], (unsigned)__popc(m));
            bin = k4.z >> 20; m = __match_any_sync(act, bin);
            if ((int)(__ffs(m) - 1) == lane) atomicAdd(&hist[bin], (unsigned)__popc(m));
            bin = k4.w >> 20; m = __match_any_sync(act, bin);
            if ((int)(__ffs(m) - 1) == lane) atomicAdd(&hist[bin], (unsigned)__popc(m));
        }
    }
    #pragma unroll
    for (int d = 16; d > 0; d >>= 1) {
        psum += __shfl_down_sync(0xffffffffu, psum, d);
        pcnt += __shfl_down_sync(0xffffffffu, pcnt, d);
    }
    if (lane == 0) { s_wf[wrp] = psum; s_wi[wrp] = pcnt; }
    __syncthreads();
    if (wrp == 0) {
        float f = s_wf[lane];
        int   c = s_wi[lane];
        #pragma unroll
        for (int d = 16; d > 0; d >>= 1) {
            f += __shfl_down_sync(0xffffffffu, f, d);
            c += __shfl_down_sync(0xffffffffu, c, d);
        }
        if (lane == 0) { s_pos = f; s_np = c; }
    }
    __syncthreads();

    const int np = s_np;
    const int k  = min(3 * np, A_ - 1);

    float topk = 0.0f;
    unsigned int pref24 = 0;
    if (k > 0) {
        unsigned int pref12 = 0;
        int kk = k;

        #pragma unroll
        for (int pass = 0; pass < 2; pass++) {
            if (pass == 1) {
                __syncthreads();
                ((uint4*)hist)[tid] = make_uint4(0, 0, 0, 0);
                __syncthreads();
                for (int i4 = tid; i4 < N4; i4 += K2T) {
                    uint4 k4 = keys4[i4];
                    if ((k4.x >> 20) == pref12) atomicAdd(&hist[(k4.x >> 8) & 0xFFFu], 1u);
                    if ((k4.y >> 20) == pref12) atomicAdd(&hist[(k4.y >> 8) & 0xFFFu], 1u);
                    if ((k4.z >> 20) == pref12) atomicAdd(&hist[(k4.z >> 8) & 0xFFFu], 1u);
                    if ((k4.w >> 20) == pref12) atomicAdd(&hist[(k4.w >> 8) & 0xFFFu], 1u);
                }
            }
            __syncthreads();

            uint4 h4 = ((uint4*)hist)[tid];
            int c = (int)(h4.x + h4.y + h4.z + h4.w);
            int incl = c;
            #pragma unroll
            for (int d = 1; d < 32; d <<= 1) {
                int v = __shfl_down_sync(0xffffffffu, incl, d);
                if (lane + d < 32) incl += v;
            }
            if (lane == 0) s_wi[wrp] = incl;
            __syncthreads();
            if (wrp == 0) {
                int v = s_wi[lane];
                int suf = v;
                #pragma unroll
                for (int d = 1; d < 32; d <<= 1) {
                    int u = __shfl_down_sync(0xffffffffu, suf, d);
                    if (lane + d < 32) suf += u;
                }
                s_woff[lane] = suf - v;
            }
            __syncthreads();
            const int above = incl - c + s_woff[wrp];
            if (above < kk && above + c >= kk) {
                unsigned int hv[4] = {h4.x, h4.y, h4.z, h4.w};
                int cum = above;
                #pragma unroll
                for (int j = 3; j >= 0; j--) {
                    int h = (int)hv[j];
                    cum += h;
                    if (cum >= kk) {
                        s_pref = (unsigned int)(tid * 4 + j);
                        s_kk   = kk - (cum - h);
                        break;
                    }
                }
            }
            __syncthreads();
            if (pass == 0) { pref12 = s_pref; }
            else           { pref24 = (pref12 << 12) | s_pref; }
            kk = s_kk;
        }

        const unsigned int T_hi = (pref24 << 8) | 0xFFu;
        float lsum = 0.0f;
        int   lcnt = 0;
        for (int i4 = tid; i4 < N4; i4 += K2T) {
            uint4 k4 = keys4[i4];
            if (k4.x > T_hi) { lsum += key2f(k4.x); lcnt++; }
            if (k4.y > T_hi) { lsum += key2f(k4.y); lcnt++; }
            if (k4.z > T_hi) { lsum += key2f(k4.z); lcnt++; }
            if (k4.w > T_hi) { lsum += key2f(k4.w); lcnt++; }
        }
        #pragma unroll
        for (int d = 16; d > 0; d >>= 1) {
            lsum += __shfl_down_sync(0xffffffffu, lsum, d);
            lcnt += __shfl_down_sync(0xffffffffu, lcnt, d);
        }
        if (lane == 0) { s_wf[wrp] = lsum; s_wi[wrp] = lcnt; }
        __syncthreads();
        if (wrp == 0) {
            float f = s_wf[lane];
            int   c = s_wi[lane];
            #pragma unroll
            for (int d = 16; d > 0; d >>= 1) {
                f += __shfl_down_sync(0xffffffffu, f, d);
                c += __shfl_down_sync(0xffffffffu, c, d);
            }
            if (lane == 0) s_wf[0] = f + (float)(k - c) * key2f(pref24 << 8);
        }
        __syncthreads();
        topk = s_wf[0];
    }

    if (tid == 0) {
        g_batch_loss[b] = s_pos + topk;
        g_batch_np[b]   = np;
        __threadfence();
        int t = atomicAdd(&g_ticket, 1);
        s_last = (t == B_ - 1) ? 1 : 0;
    }
    __syncthreads();

    if (s_last) {
        if (tid < B_) {
            s_red64f[tid] = *((volatile float*)&g_batch_loss[tid]);
            s_red64i[tid] = max(*((volatile int*)&g_batch_np[tid]), 1);
        }
        __syncthreads();
        for (int off = B_ / 2; off > 0; off >>= 1) {
            if (tid < off) { s_red64f[tid] += s_red64f[tid + off]; s_red64i[tid] += s_red64i[tid + off]; }
            __syncthreads();
        }
        if (tid == 0) {
            out[0] = s_red64f[0] / (float)s_red64i[0];
            g_ticket = 0;   // reset for next graph replay (deterministic)
        }
    }
}

extern "C" void kernel_launch(void* const* d_in, const int* in_sizes, int n_in,
                              void* d_out, int out_size)
{
    const float4* pred_boxes  = (const float4*)d_in[0];  // [B,A,4]
    const float*  pred_scores = (const float*)d_in[1];   // [B,A,C]
    const float4* gt_boxes    = (const float4*)d_in[2];  // [B,G,4]
    const int*    gt_labels   = (const int*)d_in[3];     // [B,G]

    cudaFuncSetAttribute(k1_anchor, cudaFuncAttributeMaxDynamicSharedMemorySize,
                         DYNSMEM);
    k1_anchor<<<NBLK, K1T, DYNSMEM>>>(pred_boxes, pred_scores, gt_boxes, gt_labels);
    k2_select<<<B_, K2T>>>((float*)d_out);
}

// round 15
// speedup vs baseline: 1.0303x; 1.0303x over previous
#include <cuda_runtime.h>
#include <math.h>
#include <stdint.h>

#define B_ 64
#define A_ 8732
#define G_ 50
#define C_ 81

// ---- K1: flattened balanced grid; warp-private 3-deep cp.async pipelines ----
#define TILE8 8
#define NTB 1092                        // ceil(8732/8) tiles per batch
#define TOT_T (B_ * NTB)                // 69888 global tiles
#define NBLK 444                        // 3 blocks/SM * 148 -> exactly one wave
#define WPB 8                           // warps per block
#define K1T (WPB * 32)                  // 256
#define NBUF 3
#define ROWF (TILE8 * C_)               // 648 floats (2592 B) per tile buffer
#define BUFB (ROWF * 4)
#define WARPB (NBUF * BUFB)             // 7776 B per warp
#define DYNSMEM (WPB * WARPB)           // 62208 B

// ---- K2 config ----
#define K2T 1024
#define NWARP (K2T / 32)
#define N4 (A_ / 4)                     // 2183 float4/uint4 per batch

// Scratch (no device alloc allowed).
//   negative anchor: v = conf >= 0
//   positive anchor: v = -(sl1 + conf) - 2  (<= -2, disjoint)
__device__ float g_work[B_ * A_];
__device__ float g_batch_loss[B_];
__device__ int   g_batch_np[B_];
__device__ int   g_ticket = 0;

__device__ __forceinline__ float fast_ex2(float x)
{
    float r;
    asm("ex2.approx.ftz.f32 %0, %1;" : "=f"(r) : "f"(x));
    return r;
}
__device__ __forceinline__ float fast_rcp(float x)
{
    float r;
    asm("rcp.approx.ftz.f32 %0, %1;" : "=f"(r) : "f"(x));
    return r;
}
__device__ __forceinline__ uint32_t smem_u32(const void* p)
{
    uint32_t a;
    asm("{ .reg .u64 t; cvta.to.shared.u64 t, %1; cvt.u32.u64 %0, t; }" : "=r"(a) : "l"(p));
    return a;
}
__device__ __forceinline__ void cp16(uint32_t dst, const void* src)
{
    asm volatile("cp.async.cg.shared.global [%0], [%1], 16;" :: "r"(dst), "l"(src));
}

#define ADV(bb, tt) { tt += WPB; if (tt >= NTB) { tt -= NTB; bb++; } }

// ---------------------------------------------------------------------------
// K1: 444 blocks, each a contiguous chunk of the flattened tile list (crosses
// <=1 batch boundary; both batches' GT data staged up-front). Each warp owns
// a 3-deep cp.async pipeline of 8-anchor tiles. Four lanes serve one anchor:
// quarter q splits the 50 GTs (13/13/12/12) and 81 classes (21/20/20/20).
// IoU argmax via inter*rcp(un) on MUFU; partials merged via two shfl_xor
// levels (lower GT index wins ties).
// ---------------------------------------------------------------------------
__global__ void __launch_bounds__(K1T, 3) k1_anchor(
    const float4* __restrict__ pred_boxes,   // [B, A, 4]
    const float*  __restrict__ pred_scores,  // [B, A, C]
    const float4* __restrict__ gt_boxes,     // [B, G, 4]
    const int*    __restrict__ gt_labels)    // [B, G]
{
    extern __shared__ __align__(16) float dyn[];          // WPB * NBUF * ROWF
    __shared__ __align__(16) float4 s_gtb[2][G_];
    __shared__ float s_gta[2][G_];
    __shared__ int   s_gl[2][G_];

    const int tid  = threadIdx.x;
    const int lane = tid & 31;
    const int wid  = tid >> 5;
    const int al   = lane & 7;      // anchor slot in tile
    const int q    = lane >> 3;     // quarter 0..3

    const int t0 = (int)((long)blockIdx.x * TOT_T / NBLK);
    const int t1 = (int)((long)(blockIdx.x + 1) * TOT_T / NBLK);
    const int b_lo = t0 / NTB;
    const int b_hi = (t1 - 1) / NTB;   // b_lo or b_lo+1

    if (tid < G_) {
        #pragma unroll
        for (int j = 0; j < 2; j++) {
            int bb = (j == 0) ? b_lo : b_hi;
            float4 g = gt_boxes[bb * G_ + tid];
            s_gtb[j][tid] = g;
            s_gta[j][tid] = (g.z - g.x) * (g.w - g.y);
            s_gl[j][tid]  = gt_labels[bb * G_ + tid];
        }
    }
    __syncthreads();

    const int gbase = (q < 2) ? q * 13 : 26 + (q - 2) * 12;   // 0,13,26,38
    const int gext  = (q < 2);                                // 13th GT
    const int cbase = (q == 0) ? 0 : 21 + (q - 1) * 20;       // 0,21,41,61

    const uint32_t wbase = smem_u32(dyn) + wid * WARPB;
    const float*   wrow  = dyn + wid * (NBUF * ROWF);
    const float L2E = 1.4426950408889634f;

    auto prefetch = [&](int bb, int til, int sel) {
        const int nA = (til == NTB - 1) ? (A_ - (NTB - 1) * TILE8) : TILE8;
        const int n4 = (nA * C_) >> 2;     // 162 or 81
        const float4* src = (const float4*)(pred_scores +
                              ((size_t)bb * A_ + (size_t)til * TILE8) * C_);
        const uint32_t dst = wbase + sel * BUFB;
        #pragma unroll
        for (int i = lane; i < ROWF / 4; i += 32)
            if (i < n4) cp16(dst + i * 16, src + i);
    };

    const int tg = t0 + wid;
    int bc = tg / NTB, tc = tg - bc * NTB;   // compute tracker
    int bp = bc, tp = tc;                    // prefetch tracker

    #pragma unroll
    for (int j = 0; j < NBUF - 1; j++) {
        if (tg + j * WPB < t1) prefetch(bp, tp, j);
        asm volatile("cp.async.commit_group;");
        ADV(bp, tp);
    }

    int sel = 0, psel = NBUF - 1;
    for (int t = tg; t < t1; t += WPB) {
        const int nA = (tc == NTB - 1) ? (A_ - (NTB - 1) * TILE8) : TILE8;
        const int ac = min(al, nA - 1);          // clamped, lanes stay convergent
        const int anchor = tc * TILE8 + ac;
        const int bo = bc - b_lo;                // 0 or 1

        const float4 pb = __ldg(pred_boxes + (size_t)bc * A_ + anchor);

        if (t + (NBUF - 1) * WPB < t1) prefetch(bp, tp, psel);
        asm volatile("cp.async.commit_group;");
        asm volatile("cp.async.wait_group 2;");
        __syncwarp();

        const float area_a = (pb.z - pb.x) * (pb.w - pb.y);

        // ---- IoU ratio argmax over this quarter's 12-13 GTs (rcp.approx) ----
        float best = -1e30f;
        int bidx = gbase;
        #pragma unroll
        for (int g = 0; g < 12; g++) {
            float4 gb = s_gtb[bo][gbase + g];
            float iw = fmaxf(fminf(pb.z, gb.z) - fmaxf(pb.x, gb.x), 0.0f);
            float ih = fminf(pb.w, gb.w) - fmaxf(pb.y, gb.y);
            float inter = iw * ih;
            float un = (area_a + s_gta[bo][gbase + g]) - inter;   // > 0 always
            float r = inter * fast_rcp(un);
            if (r > best) { best = r; bidx = gbase + g; }
        }
        if (gext) {
            float4 gb = s_gtb[bo][gbase + 12];
            float iw = fmaxf(fminf(pb.z, gb.z) - fmaxf(pb.x, gb.x), 0.0f);
            float ih = fminf(pb.w, gb.w) - fmaxf(pb.y, gb.y);
            float inter = iw * ih;
            float un = (area_a + s_gta[bo][gbase + 12]) - inter;
            float r = inter * fast_rcp(un);
            if (r > best) { best = r; bidx = gbase + 12; }
        }
        // merge quarters (lower index wins ties -> argmax-first semantics)
        #pragma unroll
        for (int off = 8; off <= 16; off <<= 1) {
            float ob = __shfl_xor_sync(0xffffffffu, best, off);
            int   ox = __shfl_xor_sync(0xffffffffu, bidx, off);
            if (ob > best || (ob == best && ox < bidx)) { best = ob; bidx = ox; }
        }
        const bool pos = best > 0.5f;
        const int  tl  = pos ? s_gl[bo][bidx] : 0;

        // ---- softmax quarter: 20(+1) classes from this warp's smem tile ----
        const float* row = wrow + sel * ROWF + ac * C_;
        float s0 = 0.0f, s1 = 0.0f;
        #pragma unroll
        for (int j = 0; j < 20; j += 2) {
            s0 += fast_ex2(row[cbase + j]     * L2E);
            s1 += fast_ex2(row[cbase + j + 1] * L2E);
        }
        float s = s0 + s1;
        if (q == 0) s += fast_ex2(row[20] * L2E);
        s += __shfl_xor_sync(0xffffffffu, s, 8);
        s += __shfl_xor_sync(0xffffffffu, s, 16);
        const float conf = __logf(s) - row[tl];

        // ---- emit (quarter 0, valid lanes only) ----
        if (q == 0 && al < nA) {
            float outv;
            if (tl > 0) {
                float4 gb = s_gtb[bo][bidx];
                float sl1 = 0.0f, d, ad;
                d = pb.x - gb.x; ad = fabsf(d); sl1 += (ad < 1.0f) ? 0.5f * d * d : ad - 0.5f;
                d = pb.y - gb.y; ad = fabsf(d); sl1 += (ad < 1.0f) ? 0.5f * d * d : ad - 0.5f;
                d = pb.z - gb.z; ad = fabsf(d); sl1 += (ad < 1.0f) ? 0.5f * d * d : ad - 0.5f;
                d = pb.w - gb.w; ad = fabsf(d); sl1 += (ad < 1.0f) ? 0.5f * d * d : ad - 0.5f;
                outv = -(sl1 + conf) - 2.0f;
            } else {
                outv = conf;
            }
            g_work[(size_t)bc * A_ + anchor] = outv;
        }
        __syncwarp();   // tile fully consumed before its buffer slot is reused

        sel  = (sel  == NBUF - 1) ? 0 : sel + 1;
        psel = (psel == NBUF - 1) ? 0 : psel + 1;
        ADV(bc, tc);
        ADV(bp, tp);
    }
}

// ---------------------------------------------------------------------------
// K2: per-batch block (1024 threads). PDL: launches while K1 drains, zeros
// its histogram, then cudaGridDependencySynchronize() before reading g_work.
// Vectorized load/decode/psum + plain smem-atomic hist, 2x12-bit radix-select
// with parallel suffix scans, vectorized top-k sum. Last block combines.
// ---------------------------------------------------------------------------
__device__ __forceinline__ unsigned int f2key(float f)
{
    unsigned int b = __float_as_uint(f);
    return (b & 0x80000000u) ? ~b : (b | 0x80000000u);
}
__device__ __forceinline__ float key2f(unsigned int k)
{
    unsigned int b = (k & 0x80000000u) ? (k ^ 0x80000000u) : ~k;
    return __uint_as_float(b);
}

__global__ void __launch_bounds__(K2T) k2_select(float* __restrict__ out)
{
    __shared__ __align__(16) unsigned int keys[A_];       // 34928 B
    __shared__ unsigned int hist[4096];                   // 16384 B
    __shared__ float s_wf[NWARP];
    __shared__ int   s_wi[NWARP];
    __shared__ int   s_woff[NWARP];
    __shared__ unsigned int s_pref;
    __shared__ int   s_kk;
    __shared__ float s_pos;
    __shared__ int   s_np;
    __shared__ int   s_last;
    __shared__ float s_red64f[B_];
    __shared__ int   s_red64i[B_];

    const int b    = blockIdx.x;
    const int tid  = threadIdx.x;
    const int lane = tid & 31;
    const int wrp  = tid >> 5;

    const unsigned int NEG1_KEY = f2key(-1.0f);

    // pre-dependency work: zero histogram while K1 is still draining
    ((uint4*)hist)[tid] = make_uint4(0, 0, 0, 0);

    // wait for K1's memory (g_work) to be visible
    cudaGridDependencySynchronize();
    __syncthreads();

    const float4* gw4 = (const float4*)(g_work + (size_t)b * A_);
    uint4* keys4 = (uint4*)keys;
    float psum = 0.0f;
    int   pcnt = 0;
    for (int i4 = tid; i4 < N4; i4 += K2T) {
        float4 v4 = gw4[i4];
        uint4 k4;
        float vv; bool p;
        vv = v4.x; p = vv <= -1.5f; if (p) { psum += -(vv + 2.0f); pcnt++; }
        k4.x = p ? NEG1_KEY : f2key(vv);
        vv = v4.y; p = vv <= -1.5f; if (p) { psum += -(vv + 2.0f); pcnt++; }
        k4.y = p ? NEG1_KEY : f2key(vv);
        vv = v4.z; p = vv <= -1.5f; if (p) { psum += -(vv + 2.0f); pcnt++; }
        k4.z = p ? NEG1_KEY : f2key(vv);
        vv = v4.w; p = vv <= -1.5f; if (p) { psum += -(vv + 2.0f); pcnt++; }
        k4.w = p ? NEG1_KEY : f2key(vv);
        keys4[i4] = k4;
        atomicAdd(&hist[k4.x >> 20], 1u);
        atomicAdd(&hist[k4.y >> 20], 1u);
        atomicAdd(&hist[k4.z >> 20], 1u);
        atomicAdd(&hist[k4.w >> 20], 1u);
    }
    #pragma unroll
    for (int d = 16; d > 0; d >>= 1) {
        psum += __shfl_down_sync(0xffffffffu, psum, d);
        pcnt += __shfl_down_sync(0xffffffffu, pcnt, d);
    }
    if (lane == 0) { s_wf[wrp] = psum; s_wi[wrp] = pcnt; }
    __syncthreads();
    if (wrp == 0) {
        float f = s_wf[lane];
        int   c = s_wi[lane];
        #pragma unroll
        for (int d = 16; d > 0; d >>= 1) {
            f += __shfl_down_sync(0xffffffffu, f, d);
            c += __shfl_down_sync(0xffffffffu, c, d);
        }
        if (lane == 0) { s_pos = f; s_np = c; }
    }
    __syncthreads();

    const int np = s_np;
    const int k  = min(3 * np, A_ - 1);

    float topk = 0.0f;
    unsigned int pref24 = 0;
    if (k > 0) {
        unsigned int pref12 = 0;
        int kk = k;

        #pragma unroll
        for (int pass = 0; pass < 2; pass++) {
            if (pass == 1) {
                __syncthreads();
                ((uint4*)hist)[tid] = make_uint4(0, 0, 0, 0);
                __syncthreads();
                for (int i4 = tid; i4 < N4; i4 += K2T) {
                    uint4 k4 = keys4[i4];
                    if ((k4.x >> 20) == pref12) atomicAdd(&hist[(k4.x >> 8) & 0xFFFu], 1u);
                    if ((k4.y >> 20) == pref12) atomicAdd(&hist[(k4.y >> 8) & 0xFFFu], 1u);
                    if ((k4.z >> 20) == pref12) atomicAdd(&hist[(k4.z >> 8) & 0xFFFu], 1u);
                    if ((k4.w >> 20) == pref12) atomicAdd(&hist[(k4.w >> 8) & 0xFFFu], 1u);
                }
            }
            __syncthreads();

            uint4 h4 = ((uint4*)hist)[tid];
            int c = (int)(h4.x + h4.y + h4.z + h4.w);
            int incl = c;
            #pragma unroll
            for (int d = 1; d < 32; d <<= 1) {
                int v = __shfl_down_sync(0xffffffffu, incl, d);
                if (lane + d < 32) incl += v;
            }
            if (lane == 0) s_wi[wrp] = incl;
            __syncthreads();
            if (wrp == 0) {
                int v = s_wi[lane];
                int suf = v;
                #pragma unroll
                for (int d = 1; d < 32; d <<= 1) {
                    int u = __shfl_down_sync(0xffffffffu, suf, d);
                    if (lane + d < 32) suf += u;
                }
                s_woff[lane] = suf - v;
            }
            __syncthreads();
            const int above = incl - c + s_woff[wrp];
            if (above < kk && above + c >= kk) {
                unsigned int hv[4] = {h4.x, h4.y, h4.z, h4.w};
                int cum = above;
                #pragma unroll
                for (int j = 3; j >= 0; j--) {
                    int h = (int)hv[j];
                    cum += h;
                    if (cum >= kk) {
                        s_pref = (unsigned int)(tid * 4 + j);
                        s_kk   = kk - (cum - h);
                        break;
                    }
                }
            }
            __syncthreads();
            if (pass == 0) { pref12 = s_pref; }
            else           { pref24 = (pref12 << 12) | s_pref; }
            kk = s_kk;
        }

        const unsigned int T_hi = (pref24 << 8) | 0xFFu;
        float lsum = 0.0f;
        int   lcnt = 0;
        for (int i4 = tid; i4 < N4; i4 += K2T) {
            uint4 k4 = keys4[i4];
            if (k4.x > T_hi) { lsum += key2f(k4.x); lcnt++; }
            if (k4.y > T_hi) { lsum += key2f(k4.y); lcnt++; }
            if (k4.z > T_hi) { lsum += key2f(k4.z); lcnt++; }
            if (k4.w > T_hi) { lsum += key2f(k4.w); lcnt++; }
        }
        #pragma unroll
        for (int d = 16; d > 0; d >>= 1) {
            lsum += __shfl_down_sync(0xffffffffu, lsum, d);
            lcnt += __shfl_down_sync(0xffffffffu, lcnt, d);
        }
        if (lane == 0) { s_wf[wrp] = lsum; s_wi[wrp] = lcnt; }
        __syncthreads();
        if (wrp == 0) {
            float f = s_wf[lane];
            int   c = s_wi[lane];
            #pragma unroll
            for (int d = 16; d > 0; d >>= 1) {
                f += __shfl_down_sync(0xffffffffu, f, d);
                c += __shfl_down_sync(0xffffffffu, c, d);
            }
            if (lane == 0) s_wf[0] = f + (float)(k - c) * key2f(pref24 << 8);
        }
        __syncthreads();
        topk = s_wf[0];
    }

    if (tid == 0) {
        g_batch_loss[b] = s_pos + topk;
        g_batch_np[b]   = np;
        __threadfence();
        int t = atomicAdd(&g_ticket, 1);
        s_last = (t == B_ - 1) ? 1 : 0;
    }
    __syncthreads();

    if (s_last) {
        if (tid < B_) {
            s_red64f[tid] = *((volatile float*)&g_batch_loss[tid]);
            s_red64i[tid] = max(*((volatile int*)&g_batch_np[tid]), 1);
        }
        __syncthreads();
        for (int off = B_ / 2; off > 0; off >>= 1) {
            if (tid < off) { s_red64f[tid] += s_red64f[tid + off]; s_red64i[tid] += s_red64i[tid + off]; }
            __syncthreads();
        }
        if (tid == 0) {
            out[0] = s_red64f[0] / (float)s_red64i[0];
            g_ticket = 0;   // reset for next graph replay (deterministic)
        }
    }
}

extern "C" void kernel_launch(void* const* d_in, const int* in_sizes, int n_in,
                              void* d_out, int out_size)
{
    const float4* pred_boxes  = (const float4*)d_in[0];  // [B,A,4]
    const float*  pred_scores = (const float*)d_in[1];   // [B,A,C]
    const float4* gt_boxes    = (const float4*)d_in[2];  // [B,G,4]
    const int*    gt_labels   = (const int*)d_in[3];     // [B,G]

    cudaFuncSetAttribute(k1_anchor, cudaFuncAttributeMaxDynamicSharedMemorySize,
                         DYNSMEM);
    k1_anchor<<<NBLK, K1T, DYNSMEM>>>(pred_boxes, pred_scores, gt_boxes, gt_labels);

    // K2 with Programmatic Dependent Launch: overlaps its prologue with K1's
    // tail; cudaGridDependencySynchronize() in-kernel guards the g_work read.
    cudaLaunchAttribute attrs[1];
    attrs[0].id = cudaLaunchAttributeProgrammaticStreamSerialization;
    attrs[0].val.programmaticStreamSerializationAllowed = 1;
    cudaLaunchConfig_t cfg = {};
    cfg.gridDim  = dim3(B_);
    cfg.blockDim = dim3(K2T);
    cfg.dynamicSmemBytes = 0;
    cfg.stream = 0;
    cfg.attrs = attrs;
    cfg.numAttrs = 1;
    cudaLaunchKernelEx(&cfg, k2_select, (float*)d_out);
}

// round 16
// speedup vs baseline: 1.0412x; 1.0106x over previous
#include <cuda_runtime.h>
#include <math.h>
#include <stdint.h>

#define B_ 64
#define A_ 8732
#define G_ 50
#define C_ 81

// ---- K1: flattened balanced grid; warp-private 3-deep cp.async pipelines ----
#define TILE8 8
#define NTB 1092                        // ceil(8732/8) tiles per batch
#define TOT_T (B_ * NTB)                // 69888 global tiles
#define NBLK 444                        // 3 blocks/SM * 148 -> exactly one wave
#define WPB 8                           // warps per block
#define K1T (WPB * 32)                  // 256
#define NBUF 3
#define ROWF (TILE8 * C_)               // 648 floats (2592 B) per tile buffer
#define BUFB (ROWF * 4)
#define WARPB (NBUF * BUFB)             // 7776 B per warp
#define DYNSMEM (WPB * WARPB)           // 62208 B

// ---- K2 config ----
#define K2T 1024
#define NWARP (K2T / 32)
#define N4 (A_ / 4)                     // 2183 float4/uint4 per batch

// Scratch (no device alloc allowed).
//   negative anchor: v = conf >= 0
//   positive anchor: v = -(sl1 + conf) - 2  (<= -2, disjoint)
__device__ float g_work[B_ * A_];
__device__ float g_batch_loss[B_];
__device__ int   g_batch_np[B_];
__device__ int   g_ticket = 0;

__device__ __forceinline__ float fast_ex2(float x)
{
    float r;
    asm("ex2.approx.ftz.f32 %0, %1;" : "=f"(r) : "f"(x));
    return r;
}
__device__ __forceinline__ float fast_rcp(float x)
{
    float r;
    asm("rcp.approx.ftz.f32 %0, %1;" : "=f"(r) : "f"(x));
    return r;
}
__device__ __forceinline__ uint32_t smem_u32(const void* p)
{
    uint32_t a;
    asm("{ .reg .u64 t; cvta.to.shared.u64 t, %1; cvt.u32.u64 %0, t; }" : "=r"(a) : "l"(p));
    return a;
}
__device__ __forceinline__ void cp16(uint32_t dst, const void* src)
{
    asm volatile("cp.async.cg.shared.global [%0], [%1], 16;" :: "r"(dst), "l"(src));
}

#define ADV(bb, tt) { tt += WPB; if (tt >= NTB) { tt -= NTB; bb++; } }

// ---------------------------------------------------------------------------
// K1: 444 blocks, each a contiguous chunk of the flattened tile list (crosses
// <=1 batch boundary; both batches' GT data staged up-front). Each warp owns
// a 3-deep cp.async pipeline of 8-anchor tiles with a SINGLE syncwarp per
// tile: {wait_group 1; syncwarp; prefetch+commit; compute} keeps depth-2 in
// flight while both publishing the current tile and certifying the buffer
// being overwritten was consumed. Four lanes serve one anchor: quarter q
// splits the 50 GTs (13/13/12/12) and 81 classes (21/20/20/20). IoU argmax
// via inter*rcp(un) on MUFU; partials merged via two shfl_xor levels.
// ---------------------------------------------------------------------------
__global__ void __launch_bounds__(K1T, 3) k1_anchor(
    const float4* __restrict__ pred_boxes,   // [B, A, 4]
    const float*  __restrict__ pred_scores,  // [B, A, C]
    const float4* __restrict__ gt_boxes,     // [B, G, 4]
    const int*    __restrict__ gt_labels)    // [B, G]
{
    extern __shared__ __align__(16) float dyn[];          // WPB * NBUF * ROWF
    __shared__ __align__(16) float4 s_gtb[2][G_];
    __shared__ float s_gta[2][G_];
    __shared__ int   s_gl[2][G_];

    const int tid  = threadIdx.x;
    const int lane = tid & 31;
    const int wid  = tid >> 5;
    const int al   = lane & 7;      // anchor slot in tile
    const int q    = lane >> 3;     // quarter 0..3

    const int t0 = (int)((long)blockIdx.x * TOT_T / NBLK);
    const int t1 = (int)((long)(blockIdx.x + 1) * TOT_T / NBLK);
    const int b_lo = t0 / NTB;
    const int b_hi = (t1 - 1) / NTB;   // b_lo or b_lo+1

    if (tid < G_) {
        #pragma unroll
        for (int j = 0; j < 2; j++) {
            int bb = (j == 0) ? b_lo : b_hi;
            float4 g = gt_boxes[bb * G_ + tid];
            s_gtb[j][tid] = g;
            s_gta[j][tid] = (g.z - g.x) * (g.w - g.y);
            s_gl[j][tid]  = gt_labels[bb * G_ + tid];
        }
    }
    __syncthreads();

    const int gbase = (q < 2) ? q * 13 : 26 + (q - 2) * 12;   // 0,13,26,38
    const int gext  = (q < 2);                                // 13th GT
    const int cbase = (q == 0) ? 0 : 21 + (q - 1) * 20;       // 0,21,41,61

    const uint32_t wbase = smem_u32(dyn) + wid * WARPB;
    const float*   wrow  = dyn + wid * (NBUF * ROWF);
    const float L2E = 1.4426950408889634f;

    auto prefetch = [&](int bb, int til, int sel) {
        const int nA = (til == NTB - 1) ? (A_ - (NTB - 1) * TILE8) : TILE8;
        const int n4 = (nA * C_) >> 2;     // 162 or 81
        const float4* src = (const float4*)(pred_scores +
                              ((size_t)bb * A_ + (size_t)til * TILE8) * C_);
        const uint32_t dst = wbase + sel * BUFB;
        #pragma unroll
        for (int i = lane; i < ROWF / 4; i += 32)
            if (i < n4) cp16(dst + i * 16, src + i);
    };

    const int tg = t0 + wid;
    int bc = tg / NTB, tc = tg - bc * NTB;   // compute tracker
    int bp = bc, tp = tc;                    // prefetch tracker

    // prologue: fill 2 pipeline stages
    #pragma unroll
    for (int j = 0; j < NBUF - 1; j++) {
        if (tg + j * WPB < t1) prefetch(bp, tp, j);
        asm volatile("cp.async.commit_group;");
        ADV(bp, tp);
    }

    int sel = 0, psel = NBUF - 1;
    for (int t = tg; t < t1; t += WPB) {
        const int nA = (tc == NTB - 1) ? (A_ - (NTB - 1) * TILE8) : TILE8;
        const int ac = min(al, nA - 1);          // clamped, lanes stay convergent
        const int anchor = tc * TILE8 + ac;
        const int bo = bc - b_lo;                // 0 or 1

        const float4 pb = __ldg(pred_boxes + (size_t)bc * A_ + anchor);

        // retire current tile's group, single barrier, then issue next prefetch
        asm volatile("cp.async.wait_group 1;");
        __syncwarp();
        if (t + (NBUF - 1) * WPB < t1) prefetch(bp, tp, psel);
        asm volatile("cp.async.commit_group;");

        const float area_a = (pb.z - pb.x) * (pb.w - pb.y);

        // ---- IoU ratio argmax over this quarter's 12-13 GTs (rcp.approx) ----
        float best = -1e30f;
        int bidx = gbase;
        #pragma unroll
        for (int g = 0; g < 12; g++) {
            float4 gb = s_gtb[bo][gbase + g];
            float iw = fmaxf(fminf(pb.z, gb.z) - fmaxf(pb.x, gb.x), 0.0f);
            float ih = fminf(pb.w, gb.w) - fmaxf(pb.y, gb.y);
            float inter = iw * ih;
            float un = (area_a + s_gta[bo][gbase + g]) - inter;   // > 0 always
            float r = inter * fast_rcp(un);
            if (r > best) { best = r; bidx = gbase + g; }
        }
        if (gext) {
            float4 gb = s_gtb[bo][gbase + 12];
            float iw = fmaxf(fminf(pb.z, gb.z) - fmaxf(pb.x, gb.x), 0.0f);
            float ih = fminf(pb.w, gb.w) - fmaxf(pb.y, gb.y);
            float inter = iw * ih;
            float un = (area_a + s_gta[bo][gbase + 12]) - inter;
            float r = inter * fast_rcp(un);
            if (r > best) { best = r; bidx = gbase + 12; }
        }
        // merge quarters (lower index wins ties -> argmax-first semantics)
        #pragma unroll
        for (int off = 8; off <= 16; off <<= 1) {
            float ob = __shfl_xor_sync(0xffffffffu, best, off);
            int   ox = __shfl_xor_sync(0xffffffffu, bidx, off);
            if (ob > best || (ob == best && ox < bidx)) { best = ob; bidx = ox; }
        }
        const bool pos = best > 0.5f;
        const int  tl  = pos ? s_gl[bo][bidx] : 0;

        // ---- softmax quarter: 20(+1) classes from this warp's smem tile ----
        const float* row = wrow + sel * ROWF + ac * C_;
        float s0 = 0.0f, s1 = 0.0f;
        #pragma unroll
        for (int j = 0; j < 20; j += 2) {
            s0 += fast_ex2(row[cbase + j]     * L2E);
            s1 += fast_ex2(row[cbase + j + 1] * L2E);
        }
        float s = s0 + s1;
        if (q == 0) s += fast_ex2(row[20] * L2E);
        s += __shfl_xor_sync(0xffffffffu, s, 8);
        s += __shfl_xor_sync(0xffffffffu, s, 16);
        const float conf = __logf(s) - row[tl];

        // ---- emit (quarter 0, valid lanes only) ----
        if (q == 0 && al < nA) {
            float outv;
            if (tl > 0) {
                float4 gb = s_gtb[bo][bidx];
                float sl1 = 0.0f, d, ad;
                d = pb.x - gb.x; ad = fabsf(d); sl1 += (ad < 1.0f) ? 0.5f * d * d : ad - 0.5f;
                d = pb.y - gb.y; ad = fabsf(d); sl1 += (ad < 1.0f) ? 0.5f * d * d : ad - 0.5f;
                d = pb.z - gb.z; ad = fabsf(d); sl1 += (ad < 1.0f) ? 0.5f * d * d : ad - 0.5f;
                d = pb.w - gb.w; ad = fabsf(d); sl1 += (ad < 1.0f) ? 0.5f * d * d : ad - 0.5f;
                outv = -(sl1 + conf) - 2.0f;
            } else {
                outv = conf;
            }
            g_work[(size_t)bc * A_ + anchor] = outv;
        }

        sel  = (sel  == NBUF - 1) ? 0 : sel + 1;
        psel = (psel == NBUF - 1) ? 0 : psel + 1;
        ADV(bc, tc);
        ADV(bp, tp);
    }
}

// ---------------------------------------------------------------------------
// K2: per-batch block (1024 threads). Vectorized (float4/uint4) load/decode/
// psum + plain smem-atomic hist, 2x12-bit radix-select with parallel suffix
// scans, vectorized top-k sum. Last block (atomic ticket) combines into d_out.
// ---------------------------------------------------------------------------
__device__ __forceinline__ unsigned int f2key(float f)
{
    unsigned int b = __float_as_uint(f);
    return (b & 0x80000000u) ? ~b : (b | 0x80000000u);
}
__device__ __forceinline__ float key2f(unsigned int k)
{
    unsigned int b = (k & 0x80000000u) ? (k ^ 0x80000000u) : ~k;
    return __uint_as_float(b);
}

__global__ void __launch_bounds__(K2T) k2_select(float* __restrict__ out)
{
    __shared__ __align__(16) unsigned int keys[A_];       // 34928 B
    __shared__ unsigned int hist[4096];                   // 16384 B
    __shared__ float s_wf[NWARP];
    __shared__ int   s_wi[NWARP];
    __shared__ int   s_woff[NWARP];
    __shared__ unsigned int s_pref;
    __shared__ int   s_kk;
    __shared__ float s_pos;
    __shared__ int   s_np;
    __shared__ int   s_last;
    __shared__ float s_red64f[B_];
    __shared__ int   s_red64i[B_];

    const int b    = blockIdx.x;
    const int tid  = threadIdx.x;
    const int lane = tid & 31;
    const int wrp  = tid >> 5;

    const unsigned int NEG1_KEY = f2key(-1.0f);

    ((uint4*)hist)[tid] = make_uint4(0, 0, 0, 0);
    __syncthreads();

    const float4* gw4 = (const float4*)(g_work + (size_t)b * A_);
    uint4* keys4 = (uint4*)keys;
    float psum = 0.0f;
    int   pcnt = 0;
    for (int i4 = tid; i4 < N4; i4 += K2T) {
        float4 v4 = gw4[i4];
        uint4 k4;
        float vv; bool p;
        vv = v4.x; p = vv <= -1.5f; if (p) { psum += -(vv + 2.0f); pcnt++; }
        k4.x = p ? NEG1_KEY : f2key(vv);
        vv = v4.y; p = vv <= -1.5f; if (p) { psum += -(vv + 2.0f); pcnt++; }
        k4.y = p ? NEG1_KEY : f2key(vv);
        vv = v4.z; p = vv <= -1.5f; if (p) { psum += -(vv + 2.0f); pcnt++; }
        k4.z = p ? NEG1_KEY : f2key(vv);
        vv = v4.w; p = vv <= -1.5f; if (p) { psum += -(vv + 2.0f); pcnt++; }
        k4.w = p ? NEG1_KEY : f2key(vv);
        keys4[i4] = k4;
        atomicAdd(&hist[k4.x >> 20], 1u);
        atomicAdd(&hist[k4.y >> 20], 1u);
        atomicAdd(&hist[k4.z >> 20], 1u);
        atomicAdd(&hist[k4.w >> 20], 1u);
    }
    #pragma unroll
    for (int d = 16; d > 0; d >>= 1) {
        psum += __shfl_down_sync(0xffffffffu, psum, d);
        pcnt += __shfl_down_sync(0xffffffffu, pcnt, d);
    }
    if (lane == 0) { s_wf[wrp] = psum; s_wi[wrp] = pcnt; }
    __syncthreads();
    if (wrp == 0) {
        float f = s_wf[lane];
        int   c = s_wi[lane];
        #pragma unroll
        for (int d = 16; d > 0; d >>= 1) {
            f += __shfl_down_sync(0xffffffffu, f, d);
            c += __shfl_down_sync(0xffffffffu, c, d);
        }
        if (lane == 0) { s_pos = f; s_np = c; }
    }
    __syncthreads();

    const int np = s_np;
    const int k  = min(3 * np, A_ - 1);

    float topk = 0.0f;
    unsigned int pref24 = 0;
    if (k > 0) {
        unsigned int pref12 = 0;
        int kk = k;

        #pragma unroll
        for (int pass = 0; pass < 2; pass++) {
            if (pass == 1) {
                __syncthreads();
                ((uint4*)hist)[tid] = make_uint4(0, 0, 0, 0);
                __syncthreads();
                for (int i4 = tid; i4 < N4; i4 += K2T) {
                    uint4 k4 = keys4[i4];
                    if ((k4.x >> 20) == pref12) atomicAdd(&hist[(k4.x >> 8) & 0xFFFu], 1u);
                    if ((k4.y >> 20) == pref12) atomicAdd(&hist[(k4.y >> 8) & 0xFFFu], 1u);
                    if ((k4.z >> 20) == pref12) atomicAdd(&hist[(k4.z >> 8) & 0xFFFu], 1u);
                    if ((k4.w >> 20) == pref12) atomicAdd(&hist[(k4.w >> 8) & 0xFFFu], 1u);
                }
            }
            __syncthreads();

            uint4 h4 = ((uint4*)hist)[tid];
            int c = (int)(h4.x + h4.y + h4.z + h4.w);
            int incl = c;
            #pragma unroll
            for (int d = 1; d < 32; d <<= 1) {
                int v = __shfl_down_sync(0xffffffffu, incl, d);
                if (lane + d < 32) incl += v;
            }
            if (lane == 0) s_wi[wrp] = incl;
            __syncthreads();
            if (wrp == 0) {
                int v = s_wi[lane];
                int suf = v;
                #pragma unroll
                for (int d = 1; d < 32; d <<= 1) {
                    int u = __shfl_down_sync(0xffffffffu, suf, d);
                    if (lane + d < 32) suf += u;
                }
                s_woff[lane] = suf - v;
            }
            __syncthreads();
            const int above = incl - c + s_woff[wrp];
            if (above < kk && above + c >= kk) {
                unsigned int hv[4] = {h4.x, h4.y, h4.z, h4.w};
                int cum = above;
                #pragma unroll
                for (int j = 3; j >= 0; j--) {
                    int h = (int)hv[j];
                    cum += h;
                    if (cum >= kk) {
                        s_pref = (unsigned int)(tid * 4 + j);
                        s_kk   = kk - (cum - h);
                        break;
                    }
                }
            }
            __syncthreads();
            if (pass == 0) { pref12 = s_pref; }
            else           { pref24 = (pref12 << 12) | s_pref; }
            kk = s_kk;
        }

        const unsigned int T_hi = (pref24 << 8) | 0xFFu;
        float lsum = 0.0f;
        int   lcnt = 0;
        for (int i4 = tid; i4 < N4; i4 += K2T) {
            uint4 k4 = keys4[i4];
            if (k4.x > T_hi) { lsum += key2f(k4.x); lcnt++; }
            if (k4.y > T_hi) { lsum += key2f(k4.y); lcnt++; }
            if (k4.z > T_hi) { lsum += key2f(k4.z); lcnt++; }
            if (k4.w > T_hi) { lsum += key2f(k4.w); lcnt++; }
        }
        #pragma unroll
        for (int d = 16; d > 0; d >>= 1) {
            lsum += __shfl_down_sync(0xffffffffu, lsum, d);
            lcnt += __shfl_down_sync(0xffffffffu, lcnt, d);
        }
        if (lane == 0) { s_wf[wrp] = lsum; s_wi[wrp] = lcnt; }
        __syncthreads();
        if (wrp == 0) {
            float f = s_wf[lane];
            int   c = s_wi[lane];
            #pragma unroll
            for (int d = 16; d > 0; d >>= 1) {
                f += __shfl_down_sync(0xffffffffu, f, d);
                c += __shfl_down_sync(0xffffffffu, c, d);
            }
            if (lane == 0) s_wf[0] = f + (float)(k - c) * key2f(pref24 << 8);
        }
        __syncthreads();
        topk = s_wf[0];
    }

    if (tid == 0) {
        g_batch_loss[b] = s_pos + topk;
        g_batch_np[b]   = np;
        __threadfence();
        int t = atomicAdd(&g_ticket, 1);
        s_last = (t == B_ - 1) ? 1 : 0;
    }
    __syncthreads();

    if (s_last) {
        if (tid < B_) {
            s_red64f[tid] = *((volatile float*)&g_batch_loss[tid]);
            s_red64i[tid] = max(*((volatile int*)&g_batch_np[tid]), 1);
        }
        __syncthreads();
        for (int off = B_ / 2; off > 0; off >>= 1) {
            if (tid < off) { s_red64f[tid] += s_red64f[tid + off]; s_red64i[tid] += s_red64i[tid + off]; }
            __syncthreads();
        }
        if (tid == 0) {
            out[0] = s_red64f[0] / (float)s_red64i[0];
            g_ticket = 0;   // reset for next graph replay (deterministic)
        }
    }
}

extern "C" void kernel_launch(void* const* d_in, const int* in_sizes, int n_in,
                              void* d_out, int out_size)
{
    const float4* pred_boxes  = (const float4*)d_in[0];  // [B,A,4]
    const float*  pred_scores = (const float*)d_in[1];   // [B,A,C]
    const float4* gt_boxes    = (const float4*)d_in[2];  // [B,G,4]
    const int*    gt_labels   = (const int*)d_in[3];     // [B,G]

    cudaFuncSetAttribute(k1_anchor, cudaFuncAttributeMaxDynamicSharedMemorySize,
                         DYNSMEM);
    k1_anchor<<<NBLK, K1T, DYNSMEM>>>(pred_boxes, pred_scores, gt_boxes, gt_labels);
    k2_select<<<B_, K2T>>>((float*)d_out);
}

// round 17
// speedup vs baseline: 1.0446x; 1.0033x over previous
#include <cuda_runtime.h>
#include <math.h>
#include <stdint.h>

#define B_ 64
#define A_ 8732
#define G_ 50
#define C_ 81

// ---- K1: flattened balanced grid; warp-private 3-deep cp.async pipelines ----
#define TILE8 8
#define NTB 1092                        // ceil(8732/8) tiles per batch
#define TOT_T (B_ * NTB)                // 69888 global tiles
#define NBLK 444                        // 3 blocks/SM * 148 -> exactly one wave
#define WPB 8                           // warps per block
#define K1T (WPB * 32)                  // 256
#define NBUF 3
#define ROWF (TILE8 * C_)               // 648 floats (2592 B) per tile buffer
#define BUFB (ROWF * 4)
#define WARPB (NBUF * BUFB)             // 7776 B per warp
#define DYNSMEM (WPB * WARPB)           // 62208 B

// ---- K2 config ----
#define K2T 1024
#define NWARP (K2T / 32)
#define N4 (A_ / 4)                     // 2183 float4/uint4 per batch
#define K2_IT 3                         // ceil(2183/1024)

// Scratch (no device alloc allowed).
//   negative anchor: v = conf >= 0
//   positive anchor: v = -(sl1 + conf) - 2  (<= -2, disjoint)
__device__ float g_work[B_ * A_];
__device__ float g_batch_loss[B_];
__device__ int   g_batch_np[B_];
__device__ int   g_ticket = 0;

__device__ __forceinline__ float fast_ex2(float x)
{
    float r;
    asm("ex2.approx.ftz.f32 %0, %1;" : "=f"(r) : "f"(x));
    return r;
}
__device__ __forceinline__ float fast_rcp(float x)
{
    float r;
    asm("rcp.approx.ftz.f32 %0, %1;" : "=f"(r) : "f"(x));
    return r;
}
__device__ __forceinline__ uint32_t smem_u32(const void* p)
{
    uint32_t a;
    asm("{ .reg .u64 t; cvta.to.shared.u64 t, %1; cvt.u32.u64 %0, t; }" : "=r"(a) : "l"(p));
    return a;
}
__device__ __forceinline__ void cp16(uint32_t dst, const void* src)
{
    asm volatile("cp.async.cg.shared.global [%0], [%1], 16;" :: "r"(dst), "l"(src));
}

#define ADV(bb, tt) { tt += WPB; if (tt >= NTB) { tt -= NTB; bb++; } }

// ---------------------------------------------------------------------------
// K1: 444 blocks, each a contiguous chunk of the flattened tile list (crosses
// <=1 batch boundary; both batches' GT data staged up-front). Each warp owns
// a 3-deep cp.async pipeline of 8-anchor tiles with a SINGLE syncwarp per
// tile. Four lanes serve one anchor: quarter q splits the 50 GTs
// (13/13/12/12) and 81 classes (21/20/20/20). IoU argmax via inter*rcp(un)
// on MUFU; partials merged via two shfl_xor levels.
// ---------------------------------------------------------------------------
__global__ void __launch_bounds__(K1T, 3) k1_anchor(
    const float4* __restrict__ pred_boxes,   // [B, A, 4]
    const float*  __restrict__ pred_scores,  // [B, A, C]
    const float4* __restrict__ gt_boxes,     // [B, G, 4]
    const int*    __restrict__ gt_labels)    // [B, G]
{
    extern __shared__ __align__(16) float dyn[];          // WPB * NBUF * ROWF
    __shared__ __align__(16) float4 s_gtb[2][G_];
    __shared__ float s_gta[2][G_];
    __shared__ int   s_gl[2][G_];

    const int tid  = threadIdx.x;
    const int lane = tid & 31;
    const int wid  = tid >> 5;
    const int al   = lane & 7;      // anchor slot in tile
    const int q    = lane >> 3;     // quarter 0..3

    const int t0 = (int)((long)blockIdx.x * TOT_T / NBLK);
    const int t1 = (int)((long)(blockIdx.x + 1) * TOT_T / NBLK);
    const int b_lo = t0 / NTB;
    const int b_hi = (t1 - 1) / NTB;   // b_lo or b_lo+1

    if (tid < G_) {
        #pragma unroll
        for (int j = 0; j < 2; j++) {
            int bb = (j == 0) ? b_lo : b_hi;
            float4 g = gt_boxes[bb * G_ + tid];
            s_gtb[j][tid] = g;
            s_gta[j][tid] = (g.z - g.x) * (g.w - g.y);
            s_gl[j][tid]  = gt_labels[bb * G_ + tid];
        }
    }
    __syncthreads();

    const int gbase = (q < 2) ? q * 13 : 26 + (q - 2) * 12;   // 0,13,26,38
    const int gext  = (q < 2);                                // 13th GT
    const int cbase = (q == 0) ? 0 : 21 + (q - 1) * 20;       // 0,21,41,61

    const uint32_t wbase = smem_u32(dyn) + wid * WARPB;
    const float*   wrow  = dyn + wid * (NBUF * ROWF);
    const float L2E = 1.4426950408889634f;

    auto prefetch = [&](int bb, int til, int sel) {
        const int nA = (til == NTB - 1) ? (A_ - (NTB - 1) * TILE8) : TILE8;
        const int n4 = (nA * C_) >> 2;     // 162 or 81
        const float4* src = (const float4*)(pred_scores +
                              ((size_t)bb * A_ + (size_t)til * TILE8) * C_);
        const uint32_t dst = wbase + sel * BUFB;
        #pragma unroll
        for (int i = lane; i < ROWF / 4; i += 32)
            if (i < n4) cp16(dst + i * 16, src + i);
    };

    const int tg = t0 + wid;
    int bc = tg / NTB, tc = tg - bc * NTB;   // compute tracker
    int bp = bc, tp = tc;                    // prefetch tracker

    // prologue: fill 2 pipeline stages
    #pragma unroll
    for (int j = 0; j < NBUF - 1; j++) {
        if (tg + j * WPB < t1) prefetch(bp, tp, j);
        asm volatile("cp.async.commit_group;");
        ADV(bp, tp);
    }

    int sel = 0, psel = NBUF - 1;
    for (int t = tg; t < t1; t += WPB) {
        const int nA = (tc == NTB - 1) ? (A_ - (NTB - 1) * TILE8) : TILE8;
        const int ac = min(al, nA - 1);          // clamped, lanes stay convergent
        const int anchor = tc * TILE8 + ac;
        const int bo = bc - b_lo;                // 0 or 1

        const float4 pb = __ldg(pred_boxes + (size_t)bc * A_ + anchor);

        // retire current tile's group, single barrier, then issue next prefetch
        asm volatile("cp.async.wait_group 1;");
        __syncwarp();
        if (t + (NBUF - 1) * WPB < t1) prefetch(bp, tp, psel);
        asm volatile("cp.async.commit_group;");

        const float area_a = (pb.z - pb.x) * (pb.w - pb.y);

        // ---- IoU ratio argmax over this quarter's 12-13 GTs (rcp.approx) ----
        float best = -1e30f;
        int bidx = gbase;
        #pragma unroll
        for (int g = 0; g < 12; g++) {
            float4 gb = s_gtb[bo][gbase + g];
            float iw = fmaxf(fminf(pb.z, gb.z) - fmaxf(pb.x, gb.x), 0.0f);
            float ih = fminf(pb.w, gb.w) - fmaxf(pb.y, gb.y);
            float inter = iw * ih;
            float un = (area_a + s_gta[bo][gbase + g]) - inter;   // > 0 always
            float r = inter * fast_rcp(un);
            if (r > best) { best = r; bidx = gbase + g; }
        }
        if (gext) {
            float4 gb = s_gtb[bo][gbase + 12];
            float iw = fmaxf(fminf(pb.z, gb.z) - fmaxf(pb.x, gb.x), 0.0f);
            float ih = fminf(pb.w, gb.w) - fmaxf(pb.y, gb.y);
            float inter = iw * ih;
            float un = (area_a + s_gta[bo][gbase + 12]) - inter;
            float r = inter * fast_rcp(un);
            if (r > best) { best = r; bidx = gbase + 12; }
        }
        // merge quarters (lower index wins ties -> argmax-first semantics)
        #pragma unroll
        for (int off = 8; off <= 16; off <<= 1) {
            float ob = __shfl_xor_sync(0xffffffffu, best, off);
            int   ox = __shfl_xor_sync(0xffffffffu, bidx, off);
            if (ob > best || (ob == best && ox < bidx)) { best = ob; bidx = ox; }
        }
        const bool pos = best > 0.5f;
        const int  tl  = pos ? s_gl[bo][bidx] : 0;

        // ---- softmax quarter: 20(+1) classes from this warp's smem tile ----
        const float* row = wrow + sel * ROWF + ac * C_;
        float s0 = 0.0f, s1 = 0.0f;
        #pragma unroll
        for (int j = 0; j < 20; j += 2) {
            s0 += fast_ex2(row[cbase + j]     * L2E);
            s1 += fast_ex2(row[cbase + j + 1] * L2E);
        }
        float s = s0 + s1;
        if (q == 0) s += fast_ex2(row[20] * L2E);
        s += __shfl_xor_sync(0xffffffffu, s, 8);
        s += __shfl_xor_sync(0xffffffffu, s, 16);
        const float conf = __logf(s) - row[tl];

        // ---- emit (quarter 0, valid lanes only) ----
        if (q == 0 && al < nA) {
            float outv;
            if (tl > 0) {
                float4 gb = s_gtb[bo][bidx];
                float sl1 = 0.0f, d, ad;
                d = pb.x - gb.x; ad = fabsf(d); sl1 += (ad < 1.0f) ? 0.5f * d * d : ad - 0.5f;
                d = pb.y - gb.y; ad = fabsf(d); sl1 += (ad < 1.0f) ? 0.5f * d * d : ad - 0.5f;
                d = pb.z - gb.z; ad = fabsf(d); sl1 += (ad < 1.0f) ? 0.5f * d * d : ad - 0.5f;
                d = pb.w - gb.w; ad = fabsf(d); sl1 += (ad < 1.0f) ? 0.5f * d * d : ad - 0.5f;
                outv = -(sl1 + conf) - 2.0f;
            } else {
                outv = conf;
            }
            g_work[(size_t)bc * A_ + anchor] = outv;
        }

        sel  = (sel  == NBUF - 1) ? 0 : sel + 1;
        psel = (psel == NBUF - 1) ? 0 : psel + 1;
        ADV(bc, tc);
        ADV(bp, tp);
    }
}

// ---------------------------------------------------------------------------
// K2: per-batch block (1024 threads). REGISTER-RESIDENT keys: each thread
// holds its 3 uint4 keys in registers across all phases (no keys smem array,
// no re-reads). Vectorized load/decode/psum + plain smem-atomic hist,
// 2x12-bit radix-select with parallel suffix scans, register top-k sum.
// Last block (atomic ticket) combines the 64 batch results into d_out.
// ---------------------------------------------------------------------------
__device__ __forceinline__ unsigned int f2key(float f)
{
    unsigned int b = __float_as_uint(f);
    return (b & 0x80000000u) ? ~b : (b | 0x80000000u);
}
__device__ __forceinline__ float key2f(unsigned int k)
{
    unsigned int b = (k & 0x80000000u) ? (k ^ 0x80000000u) : ~k;
    return __uint_as_float(b);
}

__global__ void __launch_bounds__(K2T) k2_select(float* __restrict__ out)
{
    __shared__ unsigned int hist[4096];                   // 16384 B
    __shared__ float s_wf[NWARP];
    __shared__ int   s_wi[NWARP];
    __shared__ int   s_woff[NWARP];
    __shared__ unsigned int s_pref;
    __shared__ int   s_kk;
    __shared__ float s_pos;
    __shared__ int   s_np;
    __shared__ int   s_last;
    __shared__ float s_red64f[B_];
    __shared__ int   s_red64i[B_];

    const int b    = blockIdx.x;
    const int tid  = threadIdx.x;
    const int lane = tid & 31;
    const int wrp  = tid >> 5;

    const unsigned int NEG1_KEY = f2key(-1.0f);

    ((uint4*)hist)[tid] = make_uint4(0, 0, 0, 0);
    __syncthreads();

    // ---- Phase A: load + decode into REGISTERS + psum/pcnt + pass-1 hist ----
    // Inactive slots hold key 0 (bin 0): never selected since kk <= A_-1.
    const float4* gw4 = (const float4*)(g_work + (size_t)b * A_);
    uint4 rk[K2_IT];
    float psum = 0.0f;
    int   pcnt = 0;
    #pragma unroll
    for (int it = 0; it < K2_IT; it++) {
        const int i4 = tid + it * K2T;
        uint4 k4 = make_uint4(0, 0, 0, 0);
        if (i4 < N4) {
            float4 v4 = gw4[i4];
            float vv; bool p;
            vv = v4.x; p = vv <= -1.5f; if (p) { psum += -(vv + 2.0f); pcnt++; }
            k4.x = p ? NEG1_KEY : f2key(vv);
            vv = v4.y; p = vv <= -1.5f; if (p) { psum += -(vv + 2.0f); pcnt++; }
            k4.y = p ? NEG1_KEY : f2key(vv);
            vv = v4.z; p = vv <= -1.5f; if (p) { psum += -(vv + 2.0f); pcnt++; }
            k4.z = p ? NEG1_KEY : f2key(vv);
            vv = v4.w; p = vv <= -1.5f; if (p) { psum += -(vv + 2.0f); pcnt++; }
            k4.w = p ? NEG1_KEY : f2key(vv);
            atomicAdd(&hist[k4.x >> 20], 1u);
            atomicAdd(&hist[k4.y >> 20], 1u);
            atomicAdd(&hist[k4.z >> 20], 1u);
            atomicAdd(&hist[k4.w >> 20], 1u);
        }
        rk[it] = k4;
    }
    #pragma unroll
    for (int d = 16; d > 0; d >>= 1) {
        psum += __shfl_down_sync(0xffffffffu, psum, d);
        pcnt += __shfl_down_sync(0xffffffffu, pcnt, d);
    }
    if (lane == 0) { s_wf[wrp] = psum; s_wi[wrp] = pcnt; }
    __syncthreads();
    if (wrp == 0) {
        float f = s_wf[lane];
        int   c = s_wi[lane];
        #pragma unroll
        for (int d = 16; d > 0; d >>= 1) {
            f += __shfl_down_sync(0xffffffffu, f, d);
            c += __shfl_down_sync(0xffffffffu, c, d);
        }
        if (lane == 0) { s_pos = f; s_np = c; }
    }
    __syncthreads();

    const int np = s_np;
    const int k  = min(3 * np, A_ - 1);

    float topk = 0.0f;
    unsigned int pref24 = 0;
    if (k > 0) {
        unsigned int pref12 = 0;
        int kk = k;

        #pragma unroll
        for (int pass = 0; pass < 2; pass++) {
            if (pass == 1) {
                __syncthreads();
                ((uint4*)hist)[tid] = make_uint4(0, 0, 0, 0);
                __syncthreads();
                // register keys: bin 0 dummies have prefix 0 != pref12 unless
                // pref12==0, but pref12>=0x400 for real keys (conf>=0 maps to
                // key>=0x80000000 -> top12 >= 0x800; encoded -1 -> 0x407)
                #pragma unroll
                for (int it = 0; it < K2_IT; it++) {
                    uint4 k4 = rk[it];
                    if ((k4.x >> 20) == pref12) atomicAdd(&hist[(k4.x >> 8) & 0xFFFu], 1u);
                    if ((k4.y >> 20) == pref12) atomicAdd(&hist[(k4.y >> 8) & 0xFFFu], 1u);
                    if ((k4.z >> 20) == pref12) atomicAdd(&hist[(k4.z >> 8) & 0xFFFu], 1u);
                    if ((k4.w >> 20) == pref12) atomicAdd(&hist[(k4.w >> 8) & 0xFFFu], 1u);
                }
            }
            __syncthreads();

            uint4 h4 = ((uint4*)hist)[tid];
            int c = (int)(h4.x + h4.y + h4.z + h4.w);
            int incl = c;
            #pragma unroll
            for (int d = 1; d < 32; d <<= 1) {
                int v = __shfl_down_sync(0xffffffffu, incl, d);
                if (lane + d < 32) incl += v;
            }
            if (lane == 0) s_wi[wrp] = incl;
            __syncthreads();
            if (wrp == 0) {
                int v = s_wi[lane];
                int suf = v;
                #pragma unroll
                for (int d = 1; d < 32; d <<= 1) {
                    int u = __shfl_down_sync(0xffffffffu, suf, d);
                    if (lane + d < 32) suf += u;
                }
                s_woff[lane] = suf - v;
            }
            __syncthreads();
            const int above = incl - c + s_woff[wrp];
            if (above < kk && above + c >= kk) {
                unsigned int hv[4] = {h4.x, h4.y, h4.z, h4.w};
                int cum = above;
                #pragma unroll
                for (int j = 3; j >= 0; j--) {
                    int h = (int)hv[j];
                    cum += h;
                    if (cum >= kk) {
                        s_pref = (unsigned int)(tid * 4 + j);
                        s_kk   = kk - (cum - h);
                        break;
                    }
                }
            }
            __syncthreads();
            if (pass == 0) { pref12 = s_pref; }
            else           { pref24 = (pref12 << 12) | s_pref; }
            kk = s_kk;
        }

        // ---- final: register sum strictly above the 24-bit bucket ----
        const unsigned int T_hi = (pref24 << 8) | 0xFFu;
        float lsum = 0.0f;
        int   lcnt = 0;
        #pragma unroll
        for (int it = 0; it < K2_IT; it++) {
            uint4 k4 = rk[it];
            if (k4.x > T_hi) { lsum += key2f(k4.x); lcnt++; }
            if (k4.y > T_hi) { lsum += key2f(k4.y); lcnt++; }
            if (k4.z > T_hi) { lsum += key2f(k4.z); lcnt++; }
            if (k4.w > T_hi) { lsum += key2f(k4.w); lcnt++; }
        }
        #pragma unroll
        for (int d = 16; d > 0; d >>= 1) {
            lsum += __shfl_down_sync(0xffffffffu, lsum, d);
            lcnt += __shfl_down_sync(0xffffffffu, lcnt, d);
        }
        if (lane == 0) { s_wf[wrp] = lsum; s_wi[wrp] = lcnt; }
        __syncthreads();
        if (wrp == 0) {
            float f = s_wf[lane];
            int   c = s_wi[lane];
            #pragma unroll
            for (int d = 16; d > 0; d >>= 1) {
                f += __shfl_down_sync(0xffffffffu, f, d);
                c += __shfl_down_sync(0xffffffffu, c, d);
            }
            if (lane == 0) s_wf[0] = f + (float)(k - c) * key2f(pref24 << 8);
        }
        __syncthreads();
        topk = s_wf[0];
    }

    if (tid == 0) {
        g_batch_loss[b] = s_pos + topk;
        g_batch_np[b]   = np;
        __threadfence();
        int t = atomicAdd(&g_ticket, 1);
        s_last = (t == B_ - 1) ? 1 : 0;
    }
    __syncthreads();

    if (s_last) {
        if (tid < B_) {
            s_red64f[tid] = *((volatile float*)&g_batch_loss[tid]);
            s_red64i[tid] = max(*((volatile int*)&g_batch_np[tid]), 1);
        }
        __syncthreads();
        for (int off = B_ / 2; off > 0; off >>= 1) {
            if (tid < off) { s_red64f[tid] += s_red64f[tid + off]; s_red64i[tid] += s_red64i[tid + off]; }
            __syncthreads();
        }
        if (tid == 0) {
            out[0] = s_red64f[0] / (float)s_red64i[0];
            g_ticket = 0;   // reset for next graph replay (deterministic)
        }
    }
}

extern "C" void kernel_launch(void* const* d_in, const int* in_sizes, int n_in,
                              void* d_out, int out_size)
{
    const float4* pred_boxes  = (const float4*)d_in[0];  // [B,A,4]
    const float*  pred_scores = (const float*)d_in[1];   // [B,A,C]
    const float4* gt_boxes    = (const float4*)d_in[2];  // [B,G,4]
    const int*    gt_labels   = (const int*)d_in[3];     // [B,G]

    cudaFuncSetAttribute(k1_anchor, cudaFuncAttributeMaxDynamicSharedMemorySize,
                         DYNSMEM);
    k1_anchor<<<NBLK, K1T, DYNSMEM>>>(pred_boxes, pred_scores, gt_boxes, gt_labels);
    k2_select<<<B_, K2T>>>((float*)d_out);
}